// round 5
// baseline (speedup 1.0000x reference)
#include <cuda_runtime.h>
#include <cuda_bf16.h>

#define Bb 256
#define Tt 512
#define Ff 128
#define Uu 1024
#define N4 4096

typedef __nv_bfloat16 bf;

// ---------------- scratch (static device globals; no allocation) -------------
__device__ bf g_h0h[Bb * Uu]; __device__ bf g_h0l[Bb * Uu];
__device__ bf g_h1h[Bb * Uu]; __device__ bf g_h1l[Bb * Uu];
__device__ float g_c[Bb * Uu];
__device__ bf g_hsh[(size_t)Tt * Bb * Uu]; __device__ bf g_hsl[(size_t)Tt * Bb * Uu];
__device__ bf g_t1h[(size_t)Tt * Bb * Uu]; __device__ bf g_t1l[(size_t)Tt * Bb * Uu];
__device__ bf g_xh[(size_t)Bb * Tt * Ff];  __device__ bf g_xl[(size_t)Bb * Tt * Ff];
// weights transposed to [n][k] and split hi/lo
__device__ bf g_whTh[(size_t)N4 * Uu]; __device__ bf g_whTl[(size_t)N4 * Uu];
__device__ bf g_wdTh[(size_t)N4 * Uu]; __device__ bf g_wdTl[(size_t)N4 * Uu];
__device__ bf g_wxTh[(size_t)N4 * Ff]; __device__ bf g_wxTl[(size_t)N4 * Ff];
__device__ bf g_d1Th[(size_t)Uu * Uu]; __device__ bf g_d1Tl[(size_t)Uu * Uu];
__device__ bf g_d2Th[(size_t)Ff * Uu]; __device__ bf g_d2Tl[(size_t)Ff * Uu];
__device__ unsigned int g_bar;

// ---------------- helpers ----------------------------------------------------
__device__ __forceinline__ void split_bf(float v, bf& hi, bf& lo) {
    hi = __float2bfloat16_rn(v);
    lo = __float2bfloat16_rn(v - __bfloat162float(hi));
}

__device__ __forceinline__ void mma16(float c[4], const unsigned int a[4],
                                      const unsigned int b[2]) {
    asm volatile(
        "mma.sync.aligned.m16n8k16.row.col.f32.bf16.bf16.f32 "
        "{%0,%1,%2,%3}, {%4,%5,%6,%7}, {%8,%9}, {%0,%1,%2,%3};"
        : "+f"(c[0]), "+f"(c[1]), "+f"(c[2]), "+f"(c[3])
        : "r"(a[0]), "r"(a[1]), "r"(a[2]), "r"(a[3]), "r"(b[0]), "r"(b[1]));
}

__device__ __forceinline__ float sigmoidf_(float x) {
    return 1.f / (1.f + __expf(-x));
}

__device__ __forceinline__ void cpa16(void* s, const void* g) {
    // cg: bypass L1 — required: persistent kernel, h re-read across steps.
    unsigned int sa = (unsigned int)__cvta_generic_to_shared(s);
    asm volatile("cp.async.cg.shared.global [%0], [%1], 16;" :: "r"(sa), "l"(g));
}

// ---------------- prep: split to bf16 hi/lo, transpose weights ---------------
__global__ void __launch_bounds__(256) prep_kernel(
        const float* __restrict__ x,
        const float* __restrict__ ewx, const float* __restrict__ ewh,
        const float* __restrict__ dwx, const float* __restrict__ dwh,
        const float* __restrict__ d1w, const float* __restrict__ d2w) {
    int i = blockIdx.x * blockDim.x + threadIdx.x;
    if (i == 0) g_bar = 0u;
    if (i < Bb * Tt * Ff) split_bf(x[i], g_xh[i], g_xl[i]);
    if (i < N4 * Uu) {                     // i = k*4096 + n  (coalesced reads)
        int k = i >> 12, n = i & 4095;
        size_t o = (size_t)n * Uu + k;
        split_bf(ewh[i],          g_whTh[o], g_whTl[o]);
        split_bf(dwx[i] + dwh[i], g_wdTh[o], g_wdTl[o]);
    }
    if (i < N4 * Ff) {                     // i = k*4096 + n, k < 128
        int k = i >> 12, n = i & 4095;
        size_t o = (size_t)n * Ff + k;
        split_bf(ewx[i], g_wxTh[o], g_wxTl[o]);
    }
    if (i < Uu * Uu) {                     // i = k*1024 + n
        int k = i >> 10, n = i & 1023;
        size_t o = (size_t)n * Uu + k;
        split_bf(d1w[i], g_d1Th[o], g_d1Tl[o]);
    }
    if (i < Uu * Ff) {                     // i = k*128 + n
        int k = i >> 7, n = i & 127;
        size_t o = (size_t)n * Uu + k;
        split_bf(d2w[i], g_d2Th[o], g_d2Tl[o]);
    }
    if (i < Bb * Uu) {
        g_h0h[i] = __float2bfloat16(0.f); g_h0l[i] = __float2bfloat16(0.f);
        g_c[i] = 0.f;
    }
}

// ---------------- persistent recurrence kernel --------------------------------
// 128 CTAs (32 u-tiles x 4 m-tiles), 256 threads, grid barrier between steps.
// bf16x3: z = Ah@Bh + Al@Bh + Ah@Bl, fp32 accum.
struct SmP {
    bf Ah[2][64][40];                      // 10240 B (80B rows: 16B-aligned, bank-clean)
    bf Al[2][64][40];                      // 10240 B
    union {
        struct { bf Bh[2][128][40]; bf Bl[2][128][40]; } b;   // 40960 B
        float Z[64][132];                  // 33792 B (aliases B; used post-GEMM)
    } u;
};
#define SMEMP_BYTES (sizeof(SmP))

__device__ __forceinline__ void prefetch_tiles(SmP* sm, int buf,
        const bf* Ah, const bf* Al, int lda,
        const bf* Bh, const bf* Bl, int ldb, int u0, int tid) {
    {   // A: 64 rows x 32 halves = 64B/row = 4 x 16B
        int row = tid >> 2, seg = (tid & 3) * 8;
        cpa16(&sm->Ah[buf][row][seg], Ah + (size_t)row * lda + seg);
        cpa16(&sm->Al[buf][row][seg], Al + (size_t)row * lda + seg);
    }
#pragma unroll
    for (int s = 0; s < 2; s++) {          // B: 128 n-rows x 32 halves
        int idx = tid + s * 256;
        int nn = idx >> 2, seg = (idx & 3) * 8;
        int g = ((nn >> 5) << 10) + u0 + (nn & 31);   // gate*1024 + u
        cpa16(&sm->u.b.Bh[buf][nn][seg], Bh + (size_t)g * ldb + seg);
        cpa16(&sm->u.b.Bl[buf][nn][seg], Bl + (size_t)g * ldb + seg);
    }
    asm volatile("cp.async.commit_group;");
}

__global__ void __launch_bounds__(256) lstm_persist(const float* __restrict__ eb,
                                                    const float* __restrict__ db) {
    extern __shared__ char smraw[];
    SmP* sm = (SmP*)smraw;
    const int u0 = blockIdx.x * 32;
    const int m0 = blockIdx.y * 64;
    const int tid = threadIdx.x, lane = tid & 31, wid = tid >> 5;
    const int wm = wid >> 2, wn = wid & 3, r = lane >> 2, q = lane & 3;

    for (int t = 0; t < 2 * Tt; t++) {
        const int is_dec = (t >= Tt);
        const bf *hih, *hil;
        bf *hoh, *hol;
        const bf *Wh, *Wl;
        const float* bias;
        int NC, ts;
        if (is_dec) {
            ts = t - Tt;
            Wh = g_wdTh; Wl = g_wdTl; bias = db; NC = 32;
            if (ts == 0) { hih = g_h0h; hil = g_h0l; }
            else { hih = g_hsh + (size_t)(ts - 1) * Bb * Uu;
                   hil = g_hsl + (size_t)(ts - 1) * Bb * Uu; }
            hoh = g_hsh + (size_t)ts * Bb * Uu;
            hol = g_hsl + (size_t)ts * Bb * Uu;
        } else {
            ts = t;
            Wh = g_whTh; Wl = g_whTl; bias = eb; NC = 36;  // 32 h + 4 x chunks
            if (ts & 1) { hih = g_h1h; hil = g_h1l; hoh = g_h0h; hol = g_h0l; }
            else        { hih = g_h0h; hil = g_h0l; hoh = g_h1h; hol = g_h1l; }
        }

        float acc[2][4][4];
#pragma unroll
        for (int a = 0; a < 2; a++)
#pragma unroll
            for (int b = 0; b < 4; b++)
#pragma unroll
                for (int e = 0; e < 4; e++) acc[a][b][e] = 0.f;

        auto getAB = [&](int c, const bf*& Ah_, const bf*& Al_, int& lda,
                         const bf*& Bh_, const bf*& Bl_, int& ldb) {
            if (c < 32) {
                Ah_ = hih + (size_t)m0 * Uu + c * 32;
                Al_ = hil + (size_t)m0 * Uu + c * 32;
                lda = Uu;
                Bh_ = Wh + c * 32; Bl_ = Wl + c * 32; ldb = Uu;
            } else {
                int cc = c - 32;
                size_t off = (size_t)m0 * (Tt * Ff) + (size_t)ts * Ff + cc * 32;
                Ah_ = g_xh + off; Al_ = g_xl + off; lda = Tt * Ff;
                Bh_ = g_wxTh + cc * 32; Bl_ = g_wxTl + cc * 32; ldb = Ff;
            }
        };

        {   const bf *Ah_, *Al_, *Bh_, *Bl_; int lda, ldb;
            getAB(0, Ah_, Al_, lda, Bh_, Bl_, ldb);
            prefetch_tiles(sm, 0, Ah_, Al_, lda, Bh_, Bl_, ldb, u0, tid);
        }

        for (int c = 0; c < 999; c++) {
            if (c + 1 < NC) {
                const bf *Ah_, *Al_, *Bh_, *Bl_; int lda, ldb;
                getAB(c + 1, Ah_, Al_, lda, Bh_, Bl_, ldb);
                prefetch_tiles(sm, (c + 1) & 1, Ah_, Al_, lda, Bh_, Bl_, ldb, u0, tid);
                asm volatile("cp.async.wait_group 1;");
            } else {
                asm volatile("cp.async.wait_group 0;");
            }
            __syncthreads();
            const int buf = c & 1;
#pragma unroll
            for (int kh = 0; kh < 2; kh++) {
                const int kb = kh * 16;
                unsigned int ah[2][4], al[2][4];
#pragma unroll
                for (int mb = 0; mb < 2; mb++) {
                    int row = wm * 32 + mb * 16;
                    ah[mb][0] = *(const unsigned int*)&sm->Ah[buf][row + r    ][kb + 2 * q];
                    ah[mb][1] = *(const unsigned int*)&sm->Ah[buf][row + r + 8][kb + 2 * q];
                    ah[mb][2] = *(const unsigned int*)&sm->Ah[buf][row + r    ][kb + 2 * q + 8];
                    ah[mb][3] = *(const unsigned int*)&sm->Ah[buf][row + r + 8][kb + 2 * q + 8];
                    al[mb][0] = *(const unsigned int*)&sm->Al[buf][row + r    ][kb + 2 * q];
                    al[mb][1] = *(const unsigned int*)&sm->Al[buf][row + r + 8][kb + 2 * q];
                    al[mb][2] = *(const unsigned int*)&sm->Al[buf][row + r    ][kb + 2 * q + 8];
                    al[mb][3] = *(const unsigned int*)&sm->Al[buf][row + r + 8][kb + 2 * q + 8];
                }
#pragma unroll
                for (int nb = 0; nb < 4; nb++) {
                    int col = wn * 32 + nb * 8 + r;
                    unsigned int bh[2], bl[2];
                    bh[0] = *(const unsigned int*)&sm->u.b.Bh[buf][col][kb + 2 * q];
                    bh[1] = *(const unsigned int*)&sm->u.b.Bh[buf][col][kb + 2 * q + 8];
                    bl[0] = *(const unsigned int*)&sm->u.b.Bl[buf][col][kb + 2 * q];
                    bl[1] = *(const unsigned int*)&sm->u.b.Bl[buf][col][kb + 2 * q + 8];
                    mma16(acc[0][nb], ah[0], bh);
                    mma16(acc[1][nb], ah[1], bh);
                    mma16(acc[0][nb], al[0], bh);
                    mma16(acc[1][nb], al[1], bh);
                    mma16(acc[0][nb], ah[0], bl);
                    mma16(acc[1][nb], ah[1], bl);
                }
            }
            __syncthreads();
            if (c + 1 >= NC) break;
        }

        // stage z through smem (Z aliases B; cp.async fully drained, synced)
#pragma unroll
        for (int mb = 0; mb < 2; mb++)
#pragma unroll
            for (int nb = 0; nb < 4; nb++) {
                int row = wm * 32 + mb * 16 + r;
                int col = wn * 32 + nb * 8 + 2 * q;
                sm->u.Z[row    ][col    ] = acc[mb][nb][0];
                sm->u.Z[row    ][col + 1] = acc[mb][nb][1];
                sm->u.Z[row + 8][col    ] = acc[mb][nb][2];
                sm->u.Z[row + 8][col + 1] = acc[mb][nb][3];
            }
        __syncthreads();

        for (int idx = tid; idx < 64 * 32; idx += 256) {
            int i = idx >> 5, j = idx & 31;
            int u = u0 + j;
            float zi = sm->u.Z[i][j     ] + bias[u];
            float zf = sm->u.Z[i][j + 32] + bias[u + 1024];
            float zg = sm->u.Z[i][j + 64] + bias[u + 2048];
            float zo = sm->u.Z[i][j + 96] + bias[u + 3072];
            float ig = sigmoidf_(zi);
            float fg = sigmoidf_(zf);
            float gg = tanhf(zg);
            float og = sigmoidf_(zo);
            size_t gi = (size_t)(m0 + i) * Uu + u;
            float cn = fg * g_c[gi] + ig * gg;
            g_c[gi] = cn;
            float h = og * tanhf(cn);
            split_bf(h, hoh[gi], hol[gi]);
        }

        // -------- grid barrier: 128 CTAs all co-resident (1 wave on 148 SMs) --
        __syncthreads();
        if (tid == 0) {
            __threadfence();
            atomicAdd(&g_bar, 1u);
            unsigned int target = 128u * (unsigned int)(t + 1);
            while (*((volatile unsigned int*)&g_bar) < target) __nanosleep(64);
            __threadfence();
        }
        __syncthreads();
    }
}

// ---------------- dense epilogue GEMMs (bf16x3) -------------------------------
// SRC==0: t1 = split(relu(hs @ d1W + d1b)), N=1024
// SRC==1: out =          t1 @ d2W + d2b   , N=128, store permuted [T,B]->[B,T]
template <int SRC>
__global__ void __launch_bounds__(256) dense_kernel(const float* __restrict__ bias,
                                                    float* __restrict__ outp) {
    const bf* Agh = (SRC == 0) ? g_hsh : g_t1h;
    const bf* Agl = (SRC == 0) ? g_hsl : g_t1l;
    const bf* Bgh = (SRC == 0) ? g_d1Th : g_d2Th;
    const bf* Bgl = (SRC == 0) ? g_d1Tl : g_d2Tl;
    __shared__ bf Ash[64][40], Asl[64][40], Bsh[64][40], Bsl[64][40];
    const int n0 = blockIdx.x * 64;
    const int m0 = blockIdx.y * 64;
    const int tid = threadIdx.x, lane = tid & 31, wid = tid >> 5;
    const int wm = wid >> 2, wn = wid & 3, r = lane >> 2, q = lane & 3;

    float acc[2][2][4];
#pragma unroll
    for (int a = 0; a < 2; a++)
#pragma unroll
        for (int b = 0; b < 2; b++)
#pragma unroll
            for (int e = 0; e < 4; e++) acc[a][b][e] = 0.f;

    const int row = tid >> 2, seg = (tid & 3) * 8;
    for (int k0 = 0; k0 < 1024; k0 += 32) {
        __syncthreads();
        *(uint4*)&Ash[row][seg] = *(const uint4*)(Agh + (size_t)(m0 + row) * 1024 + k0 + seg);
        *(uint4*)&Asl[row][seg] = *(const uint4*)(Agl + (size_t)(m0 + row) * 1024 + k0 + seg);
        *(uint4*)&Bsh[row][seg] = *(const uint4*)(Bgh + (size_t)(n0 + row) * 1024 + k0 + seg);
        *(uint4*)&Bsl[row][seg] = *(const uint4*)(Bgl + (size_t)(n0 + row) * 1024 + k0 + seg);
        __syncthreads();
#pragma unroll
        for (int kh = 0; kh < 2; kh++) {
            const int kb = kh * 16;
            unsigned int ah[2][4], al[2][4];
#pragma unroll
            for (int mb = 0; mb < 2; mb++) {
                int rw = wm * 32 + mb * 16;
                ah[mb][0] = *(const unsigned int*)&Ash[rw + r    ][kb + 2 * q];
                ah[mb][1] = *(const unsigned int*)&Ash[rw + r + 8][kb + 2 * q];
                ah[mb][2] = *(const unsigned int*)&Ash[rw + r    ][kb + 2 * q + 8];
                ah[mb][3] = *(const unsigned int*)&Ash[rw + r + 8][kb + 2 * q + 8];
                al[mb][0] = *(const unsigned int*)&Asl[rw + r    ][kb + 2 * q];
                al[mb][1] = *(const unsigned int*)&Asl[rw + r + 8][kb + 2 * q];
                al[mb][2] = *(const unsigned int*)&Asl[rw + r    ][kb + 2 * q + 8];
                al[mb][3] = *(const unsigned int*)&Asl[rw + r + 8][kb + 2 * q + 8];
            }
#pragma unroll
            for (int nb = 0; nb < 2; nb++) {
                int col = wn * 16 + nb * 8 + r;
                unsigned int bh[2], bl[2];
                bh[0] = *(const unsigned int*)&Bsh[col][kb + 2 * q];
                bh[1] = *(const unsigned int*)&Bsh[col][kb + 2 * q + 8];
                bl[0] = *(const unsigned int*)&Bsl[col][kb + 2 * q];
                bl[1] = *(const unsigned int*)&Bsl[col][kb + 2 * q + 8];
                mma16(acc[0][nb], ah[0], bh);
                mma16(acc[1][nb], ah[1], bh);
                mma16(acc[0][nb], al[0], bh);
                mma16(acc[1][nb], al[1], bh);
                mma16(acc[0][nb], ah[0], bl);
                mma16(acc[1][nb], ah[1], bl);
            }
        }
    }

#pragma unroll
    for (int mb = 0; mb < 2; mb++)
#pragma unroll
        for (int nb = 0; nb < 2; nb++) {
            int rwb = m0 + wm * 32 + mb * 16 + r;
            int cwb = n0 + wn * 16 + nb * 8 + 2 * q;
#pragma unroll
            for (int e = 0; e < 4; e++) {
                int rr = rwb + (e >> 1) * 8;
                int cc = cwb + (e & 1);
                float v = acc[mb][nb][e] + bias[cc];
                if (SRC == 0) {
                    v = fmaxf(v, 0.f);
                    size_t o = (size_t)rr * 1024 + cc;
                    split_bf(v, g_t1h[o], g_t1l[o]);
                } else {
                    int tt = rr >> 8, bb = rr & 255;   // row = t*256 + b
                    outp[((size_t)bb * Tt + tt) * Ff + cc] = v;
                }
            }
        }
}

// ---------------- launch ------------------------------------------------------
extern "C" void kernel_launch(void* const* d_in, const int* in_sizes, int n_in,
                              void* d_out, int out_size) {
    const float* x   = (const float*)d_in[0];
    const float* ewx = (const float*)d_in[1];
    const float* ewh = (const float*)d_in[2];
    const float* eb  = (const float*)d_in[3];
    const float* dwx = (const float*)d_in[4];
    const float* dwh = (const float*)d_in[5];
    const float* db  = (const float*)d_in[6];
    const float* d1b = (const float*)d_in[8];
    const float* d1w = (const float*)d_in[7];
    const float* d2w = (const float*)d_in[9];
    const float* d2b = (const float*)d_in[10];
    float* out = (float*)d_out;

    cudaFuncSetAttribute(lstm_persist, cudaFuncAttributeMaxDynamicSharedMemorySize,
                         (int)SMEMP_BYTES);

    prep_kernel<<<(Bb * Tt * Ff + 255) / 256, 256>>>(x, ewx, ewh, dwx, dwh, d1w, d2w);

    dim3 sgrid(Uu / 32, Bb / 64);   // 128 CTAs: single wave on 148 SMs
    lstm_persist<<<sgrid, 256, SMEMP_BYTES>>>(eb, db);

    dense_kernel<0><<<dim3(1024 / 64, (Tt * Bb) / 64), 256>>>(d1b, nullptr);
    dense_kernel<1><<<dim3(128 / 64, (Tt * Bb) / 64), 256>>>(d2b, out);
}

// round 6
// speedup vs baseline: 1.3533x; 1.3533x over previous
#include <cuda_runtime.h>
#include <cuda_bf16.h>

#define Bb 256
#define Tt 512
#define Ff 128
#define Uu 1024
#define N4 4096

typedef __nv_bfloat16 bf;

// ---------------- scratch (static device globals; no allocation) -------------
__device__ bf g_h0h[Bb * Uu]; __device__ bf g_h0l[Bb * Uu];
__device__ bf g_h1h[Bb * Uu]; __device__ bf g_h1l[Bb * Uu];
__device__ bf g_hsh[(size_t)Tt * Bb * Uu]; __device__ bf g_hsl[(size_t)Tt * Bb * Uu];
__device__ bf g_t1h[(size_t)Tt * Bb * Uu]; __device__ bf g_t1l[(size_t)Tt * Bb * Uu];
__device__ bf g_xh[(size_t)Bb * Tt * Ff];  __device__ bf g_xl[(size_t)Bb * Tt * Ff];
// weights transposed to [n][k] and split hi/lo
__device__ bf g_whTh[(size_t)N4 * Uu]; __device__ bf g_whTl[(size_t)N4 * Uu];
__device__ bf g_wdTh[(size_t)N4 * Uu]; __device__ bf g_wdTl[(size_t)N4 * Uu];
__device__ bf g_wxTh[(size_t)N4 * Ff]; __device__ bf g_wxTl[(size_t)N4 * Ff];
__device__ bf g_d1Th[(size_t)Uu * Uu]; __device__ bf g_d1Tl[(size_t)Uu * Uu];
__device__ bf g_d2Th[(size_t)Ff * Uu]; __device__ bf g_d2Tl[(size_t)Ff * Uu];
__device__ unsigned int g_bar;

// ---------------- helpers ----------------------------------------------------
__device__ __forceinline__ void split_bf(float v, bf& hi, bf& lo) {
    hi = __float2bfloat16_rn(v);
    lo = __float2bfloat16_rn(v - __bfloat162float(hi));
}

__device__ __forceinline__ void mma16(float c[4], const unsigned int a[4],
                                      const unsigned int b[2]) {
    asm volatile(
        "mma.sync.aligned.m16n8k16.row.col.f32.bf16.bf16.f32 "
        "{%0,%1,%2,%3}, {%4,%5,%6,%7}, {%8,%9}, {%0,%1,%2,%3};"
        : "+f"(c[0]), "+f"(c[1]), "+f"(c[2]), "+f"(c[3])
        : "r"(a[0]), "r"(a[1]), "r"(a[2]), "r"(a[3]), "r"(b[0]), "r"(b[1]));
}

__device__ __forceinline__ float sigmoidf_(float x) {
    return 1.f / (1.f + __expf(-x));
}

__device__ __forceinline__ void cpa16(void* s, const void* g) {
    // cg: bypass L1 — required: persistent kernel, h re-read across steps.
    unsigned int sa = (unsigned int)__cvta_generic_to_shared(s);
    asm volatile("cp.async.cg.shared.global [%0], [%1], 16;" :: "r"(sa), "l"(g));
}

// ---------------- prep: split to bf16 hi/lo, transpose weights ---------------
__global__ void __launch_bounds__(256) prep_kernel(
        const float* __restrict__ x,
        const float* __restrict__ ewx, const float* __restrict__ ewh,
        const float* __restrict__ dwx, const float* __restrict__ dwh,
        const float* __restrict__ d1w, const float* __restrict__ d2w) {
    int i = blockIdx.x * blockDim.x + threadIdx.x;
    if (i == 0) g_bar = 0u;
    if (i < Bb * Tt * Ff) split_bf(x[i], g_xh[i], g_xl[i]);
    if (i < N4 * Uu) {                     // i = k*4096 + n  (coalesced reads)
        int k = i >> 12, n = i & 4095;
        size_t o = (size_t)n * Uu + k;
        split_bf(ewh[i],          g_whTh[o], g_whTl[o]);
        split_bf(dwx[i] + dwh[i], g_wdTh[o], g_wdTl[o]);
    }
    if (i < N4 * Ff) {                     // i = k*4096 + n, k < 128
        int k = i >> 12, n = i & 4095;
        size_t o = (size_t)n * Ff + k;
        split_bf(ewx[i], g_wxTh[o], g_wxTl[o]);
    }
    if (i < Uu * Uu) {                     // i = k*1024 + n
        int k = i >> 10, n = i & 1023;
        size_t o = (size_t)n * Uu + k;
        split_bf(d1w[i], g_d1Th[o], g_d1Tl[o]);
    }
    if (i < Uu * Ff) {                     // i = k*128 + n
        int k = i >> 7, n = i & 127;
        size_t o = (size_t)n * Uu + k;
        split_bf(d2w[i], g_d2Th[o], g_d2Tl[o]);
    }
    if (i < Bb * Uu) {
        g_h0h[i] = __float2bfloat16(0.f); g_h0l[i] = __float2bfloat16(0.f);
    }
}

// ---------------- persistent recurrence kernel --------------------------------
// 128 CTAs (32 u-tiles x 4 m-tiles), 256 threads, grid barrier between steps.
// bf16x3: z = Ah@Bh + Al@Bh + Ah@Bl, fp32 accum. 4-stage cp.async ring.
struct SmP {
    bf Ah[4][64][40];                      // 20480 B (80B rows: bank-conflict-free)
    bf Al[4][64][40];                      // 20480 B
    union {
        struct { bf Bh[4][128][40]; bf Bl[4][128][40]; } b;   // 81920 B
        float Z[64][132];                  // 33792 B (aliases B; used post-GEMM)
    } u;
};
#define SMEMP_BYTES (sizeof(SmP))

__device__ __forceinline__ void prefetch_tiles(SmP* sm, int st,
        const bf* Ah, const bf* Al, int lda,
        const bf* Bh, const bf* Bl, int ldb, int u0, int tid) {
    {   // A: 64 rows x 32 halves = 64B/row = 4 x 16B
        int row = tid >> 2, seg = (tid & 3) * 8;
        cpa16(&sm->Ah[st][row][seg], Ah + (size_t)row * lda + seg);
        cpa16(&sm->Al[st][row][seg], Al + (size_t)row * lda + seg);
    }
#pragma unroll
    for (int s = 0; s < 2; s++) {          // B: 128 n-rows x 32 halves
        int idx = tid + s * 256;
        int nn = idx >> 2, seg = (idx & 3) * 8;
        int g = ((nn >> 5) << 10) + u0 + (nn & 31);   // gate*1024 + u
        cpa16(&sm->u.b.Bh[st][nn][seg], Bh + (size_t)g * ldb + seg);
        cpa16(&sm->u.b.Bl[st][nn][seg], Bl + (size_t)g * ldb + seg);
    }
    asm volatile("cp.async.commit_group;");
}

__global__ void __launch_bounds__(256) lstm_persist(const float* __restrict__ eb,
                                                    const float* __restrict__ db) {
    extern __shared__ char smraw[];
    SmP* sm = (SmP*)smraw;
    const int u0 = blockIdx.x * 32;
    const int m0 = blockIdx.y * 64;
    const int tid = threadIdx.x, lane = tid & 31, wid = tid >> 5;
    const int wm = wid >> 2, wn = wid & 3, r = lane >> 2, q = lane & 3;

    float c_reg[8];                        // cell state lives in registers: the
#pragma unroll                             // CTA<->(m,u) tile map is fixed for
    for (int s = 0; s < 8; s++) c_reg[s] = 0.f;   // all 1024 steps.

    for (int t = 0; t < 2 * Tt; t++) {
        const int is_dec = (t >= Tt);
        const bf *hih, *hil;
        bf *hoh, *hol;
        const bf *Wh, *Wl;
        const float* bias;
        int NC, ts;
        if (is_dec) {
            ts = t - Tt;
            Wh = g_wdTh; Wl = g_wdTl; bias = db; NC = 32;
            if (ts == 0) { hih = g_h0h; hil = g_h0l; }
            else { hih = g_hsh + (size_t)(ts - 1) * Bb * Uu;
                   hil = g_hsl + (size_t)(ts - 1) * Bb * Uu; }
            hoh = g_hsh + (size_t)ts * Bb * Uu;
            hol = g_hsl + (size_t)ts * Bb * Uu;
        } else {
            ts = t;
            Wh = g_whTh; Wl = g_whTl; bias = eb; NC = 36;  // 32 h + 4 x chunks
            if (ts & 1) { hih = g_h1h; hil = g_h1l; hoh = g_h0h; hol = g_h0l; }
            else        { hih = g_h0h; hil = g_h0l; hoh = g_h1h; hol = g_h1l; }
        }

        float acc[2][4][4];
#pragma unroll
        for (int a = 0; a < 2; a++)
#pragma unroll
            for (int b = 0; b < 4; b++)
#pragma unroll
                for (int e = 0; e < 4; e++) acc[a][b][e] = 0.f;

        auto getAB = [&](int c, const bf*& Ah_, const bf*& Al_, int& lda,
                         const bf*& Bh_, const bf*& Bl_, int& ldb) {
            if (c < 32) {
                Ah_ = hih + (size_t)m0 * Uu + c * 32;
                Al_ = hil + (size_t)m0 * Uu + c * 32;
                lda = Uu;
                Bh_ = Wh + c * 32; Bl_ = Wl + c * 32; ldb = Uu;
            } else {
                int cc = c - 32;
                size_t off = (size_t)m0 * (Tt * Ff) + (size_t)ts * Ff + cc * 32;
                Ah_ = g_xh + off; Al_ = g_xl + off; lda = Tt * Ff;
                Bh_ = g_wxTh + cc * 32; Bl_ = g_wxTl + cc * 32; ldb = Ff;
            }
        };

        // prologue: fill 3 stages (NC >= 32 > 3 always)
#pragma unroll
        for (int p = 0; p < 3; p++) {
            const bf *Ah_, *Al_, *Bh_, *Bl_; int lda, ldb;
            getAB(p, Ah_, Al_, lda, Bh_, Bl_, ldb);
            prefetch_tiles(sm, p, Ah_, Al_, lda, Bh_, Bl_, ldb, u0, tid);
        }

        for (int c = 0; c < NC; c++) {
            asm volatile("cp.async.wait_group 2;");   // group c done (1 group/chunk)
            __syncthreads();
            if (c + 3 < NC) {
                const bf *Ah_, *Al_, *Bh_, *Bl_; int lda, ldb;
                getAB(c + 3, Ah_, Al_, lda, Bh_, Bl_, ldb);
                prefetch_tiles(sm, (c + 3) & 3, Ah_, Al_, lda, Bh_, Bl_, ldb, u0, tid);
            } else {
                asm volatile("cp.async.commit_group;");   // empty: keep group==chunk
            }
            const int st = c & 3;
#pragma unroll
            for (int kh = 0; kh < 2; kh++) {
                const int kb = kh * 16;
                unsigned int ah[2][4], al[2][4], bh[4][2], bl[4][2];
#pragma unroll
                for (int mb = 0; mb < 2; mb++) {
                    int row = wm * 32 + mb * 16;
                    ah[mb][0] = *(const unsigned int*)&sm->Ah[st][row + r    ][kb + 2 * q];
                    ah[mb][1] = *(const unsigned int*)&sm->Ah[st][row + r + 8][kb + 2 * q];
                    ah[mb][2] = *(const unsigned int*)&sm->Ah[st][row + r    ][kb + 2 * q + 8];
                    ah[mb][3] = *(const unsigned int*)&sm->Ah[st][row + r + 8][kb + 2 * q + 8];
                    al[mb][0] = *(const unsigned int*)&sm->Al[st][row + r    ][kb + 2 * q];
                    al[mb][1] = *(const unsigned int*)&sm->Al[st][row + r + 8][kb + 2 * q];
                    al[mb][2] = *(const unsigned int*)&sm->Al[st][row + r    ][kb + 2 * q + 8];
                    al[mb][3] = *(const unsigned int*)&sm->Al[st][row + r + 8][kb + 2 * q + 8];
                }
#pragma unroll
                for (int nb = 0; nb < 4; nb++) {
                    int col = wn * 32 + nb * 8 + r;
                    bh[nb][0] = *(const unsigned int*)&sm->u.b.Bh[st][col][kb + 2 * q];
                    bh[nb][1] = *(const unsigned int*)&sm->u.b.Bh[st][col][kb + 2 * q + 8];
                    bl[nb][0] = *(const unsigned int*)&sm->u.b.Bl[st][col][kb + 2 * q];
                    bl[nb][1] = *(const unsigned int*)&sm->u.b.Bl[st][col][kb + 2 * q + 8];
                }
                // pass-outer ordering: same per-accumulator sequence (hh,lh,hl)
                // as before => numerics identical; reuse distance 2 -> 8 mma.
#pragma unroll
                for (int nb = 0; nb < 4; nb++) {
                    mma16(acc[0][nb], ah[0], bh[nb]);
                    mma16(acc[1][nb], ah[1], bh[nb]);
                }
#pragma unroll
                for (int nb = 0; nb < 4; nb++) {
                    mma16(acc[0][nb], al[0], bh[nb]);
                    mma16(acc[1][nb], al[1], bh[nb]);
                }
#pragma unroll
                for (int nb = 0; nb < 4; nb++) {
                    mma16(acc[0][nb], ah[0], bl[nb]);
                    mma16(acc[1][nb], ah[1], bl[nb]);
                }
            }
        }
        asm volatile("cp.async.wait_group 0;");
        __syncthreads();                   // all compute done before Z aliases B

        // stage z through smem so each thread gathers all 4 gates of one (b,u)
#pragma unroll
        for (int mb = 0; mb < 2; mb++)
#pragma unroll
            for (int nb = 0; nb < 4; nb++) {
                int row = wm * 32 + mb * 16 + r;
                int col = wn * 32 + nb * 8 + 2 * q;
                sm->u.Z[row    ][col    ] = acc[mb][nb][0];
                sm->u.Z[row    ][col + 1] = acc[mb][nb][1];
                sm->u.Z[row + 8][col    ] = acc[mb][nb][2];
                sm->u.Z[row + 8][col + 1] = acc[mb][nb][3];
            }
        __syncthreads();

#pragma unroll
        for (int s = 0; s < 8; s++) {
            int idx = tid + s * 256;
            int i = idx >> 5, j = idx & 31;
            int u = u0 + j;
            float zi = sm->u.Z[i][j     ] + bias[u];
            float zf = sm->u.Z[i][j + 32] + bias[u + 1024];
            float zg = sm->u.Z[i][j + 64] + bias[u + 2048];
            float zo = sm->u.Z[i][j + 96] + bias[u + 3072];
            float ig = sigmoidf_(zi);
            float fg = sigmoidf_(zf);
            float gg = tanhf(zg);
            float og = sigmoidf_(zo);
            float cn = fg * c_reg[s] + ig * gg;
            c_reg[s] = cn;
            float h = og * tanhf(cn);
            size_t gi = (size_t)(m0 + i) * Uu + u;
            split_bf(h, hoh[gi], hol[gi]);
        }

        // -------- grid barrier: 128 CTAs all co-resident (1 wave on 148 SMs) --
        __syncthreads();
        if (tid == 0) {
            __threadfence();
            atomicAdd(&g_bar, 1u);
            unsigned int target = 128u * (unsigned int)(t + 1);
            while (*((volatile unsigned int*)&g_bar) < target) __nanosleep(64);
            __threadfence();
        }
        __syncthreads();
    }
}

// ---------------- dense epilogue GEMMs (bf16x3) -------------------------------
// SRC==0: t1 = split(relu(hs @ d1W + d1b)), N=1024
// SRC==1: out =          t1 @ d2W + d2b   , N=128, store permuted [T,B]->[B,T]
template <int SRC>
__global__ void __launch_bounds__(256) dense_kernel(const float* __restrict__ bias,
                                                    float* __restrict__ outp) {
    const bf* Agh = (SRC == 0) ? g_hsh : g_t1h;
    const bf* Agl = (SRC == 0) ? g_hsl : g_t1l;
    const bf* Bgh = (SRC == 0) ? g_d1Th : g_d2Th;
    const bf* Bgl = (SRC == 0) ? g_d1Tl : g_d2Tl;
    __shared__ bf Ash[64][40], Asl[64][40], Bsh[64][40], Bsl[64][40];
    const int n0 = blockIdx.x * 64;
    const int m0 = blockIdx.y * 64;
    const int tid = threadIdx.x, lane = tid & 31, wid = tid >> 5;
    const int wm = wid >> 2, wn = wid & 3, r = lane >> 2, q = lane & 3;

    float acc[2][2][4];
#pragma unroll
    for (int a = 0; a < 2; a++)
#pragma unroll
        for (int b = 0; b < 2; b++)
#pragma unroll
            for (int e = 0; e < 4; e++) acc[a][b][e] = 0.f;

    const int row = tid >> 2, seg = (tid & 3) * 8;
    for (int k0 = 0; k0 < 1024; k0 += 32) {
        __syncthreads();
        *(uint4*)&Ash[row][seg] = *(const uint4*)(Agh + (size_t)(m0 + row) * 1024 + k0 + seg);
        *(uint4*)&Asl[row][seg] = *(const uint4*)(Agl + (size_t)(m0 + row) * 1024 + k0 + seg);
        *(uint4*)&Bsh[row][seg] = *(const uint4*)(Bgh + (size_t)(n0 + row) * 1024 + k0 + seg);
        *(uint4*)&Bsl[row][seg] = *(const uint4*)(Bgl + (size_t)(n0 + row) * 1024 + k0 + seg);
        __syncthreads();
#pragma unroll
        for (int kh = 0; kh < 2; kh++) {
            const int kb = kh * 16;
            unsigned int ah[2][4], al[2][4], bh[2][2], bl[2][2];
#pragma unroll
            for (int mb = 0; mb < 2; mb++) {
                int rw = wm * 32 + mb * 16;
                ah[mb][0] = *(const unsigned int*)&Ash[rw + r    ][kb + 2 * q];
                ah[mb][1] = *(const unsigned int*)&Ash[rw + r + 8][kb + 2 * q];
                ah[mb][2] = *(const unsigned int*)&Ash[rw + r    ][kb + 2 * q + 8];
                ah[mb][3] = *(const unsigned int*)&Ash[rw + r + 8][kb + 2 * q + 8];
                al[mb][0] = *(const unsigned int*)&Asl[rw + r    ][kb + 2 * q];
                al[mb][1] = *(const unsigned int*)&Asl[rw + r + 8][kb + 2 * q];
                al[mb][2] = *(const unsigned int*)&Asl[rw + r    ][kb + 2 * q + 8];
                al[mb][3] = *(const unsigned int*)&Asl[rw + r + 8][kb + 2 * q + 8];
            }
#pragma unroll
            for (int nb = 0; nb < 2; nb++) {
                int col = wn * 16 + nb * 8 + r;
                bh[nb][0] = *(const unsigned int*)&Bsh[col][kb + 2 * q];
                bh[nb][1] = *(const unsigned int*)&Bsh[col][kb + 2 * q + 8];
                bl[nb][0] = *(const unsigned int*)&Bsl[col][kb + 2 * q];
                bl[nb][1] = *(const unsigned int*)&Bsl[col][kb + 2 * q + 8];
            }
#pragma unroll
            for (int nb = 0; nb < 2; nb++) {
                mma16(acc[0][nb], ah[0], bh[nb]);
                mma16(acc[1][nb], ah[1], bh[nb]);
            }
#pragma unroll
            for (int nb = 0; nb < 2; nb++) {
                mma16(acc[0][nb], al[0], bh[nb]);
                mma16(acc[1][nb], al[1], bh[nb]);
            }
#pragma unroll
            for (int nb = 0; nb < 2; nb++) {
                mma16(acc[0][nb], ah[0], bl[nb]);
                mma16(acc[1][nb], ah[1], bl[nb]);
            }
        }
    }

#pragma unroll
    for (int mb = 0; mb < 2; mb++)
#pragma unroll
        for (int nb = 0; nb < 2; nb++) {
            int rwb = m0 + wm * 32 + mb * 16 + r;
            int cwb = n0 + wn * 16 + nb * 8 + 2 * q;
#pragma unroll
            for (int e = 0; e < 4; e++) {
                int rr = rwb + (e >> 1) * 8;
                int cc = cwb + (e & 1);
                float v = acc[mb][nb][e] + bias[cc];
                if (SRC == 0) {
                    v = fmaxf(v, 0.f);
                    size_t o = (size_t)rr * 1024 + cc;
                    split_bf(v, g_t1h[o], g_t1l[o]);
                } else {
                    int tt = rr >> 8, bb = rr & 255;   // row = t*256 + b
                    outp[((size_t)bb * Tt + tt) * Ff + cc] = v;
                }
            }
        }
}

// ---------------- launch ------------------------------------------------------
extern "C" void kernel_launch(void* const* d_in, const int* in_sizes, int n_in,
                              void* d_out, int out_size) {
    const float* x   = (const float*)d_in[0];
    const float* ewx = (const float*)d_in[1];
    const float* ewh = (const float*)d_in[2];
    const float* eb  = (const float*)d_in[3];
    const float* dwx = (const float*)d_in[4];
    const float* dwh = (const float*)d_in[5];
    const float* db  = (const float*)d_in[6];
    const float* d1w = (const float*)d_in[7];
    const float* d1b = (const float*)d_in[8];
    const float* d2w = (const float*)d_in[9];
    const float* d2b = (const float*)d_in[10];
    float* out = (float*)d_out;

    cudaFuncSetAttribute(lstm_persist, cudaFuncAttributeMaxDynamicSharedMemorySize,
                         (int)SMEMP_BYTES);

    prep_kernel<<<(Bb * Tt * Ff + 255) / 256, 256>>>(x, ewx, ewh, dwx, dwh, d1w, d2w);

    dim3 sgrid(Uu / 32, Bb / 64);   // 128 CTAs: single wave on 148 SMs
    lstm_persist<<<sgrid, 256, SMEMP_BYTES>>>(eb, db);

    dense_kernel<0><<<dim3(1024 / 64, (Tt * Bb) / 64), 256>>>(d1b, nullptr);
    dense_kernel<1><<<dim3(128 / 64, (Tt * Bb) / 64), 256>>>(d2b, out);
}

// round 7
// speedup vs baseline: 1.3554x; 1.0015x over previous
#include <cuda_runtime.h>
#include <cuda_bf16.h>

#define Bb 256
#define Tt 512
#define Ff 128
#define Uu 1024
#define N4 4096

typedef __nv_bfloat16 bf;

// ---------------- scratch (static device globals; no allocation) -------------
__device__ bf g_h0h[Bb * Uu]; __device__ bf g_h0l[Bb * Uu];
__device__ bf g_h1h[Bb * Uu]; __device__ bf g_h1l[Bb * Uu];
__device__ bf g_hsh[(size_t)Tt * Bb * Uu]; __device__ bf g_hsl[(size_t)Tt * Bb * Uu];
__device__ bf g_t1h[(size_t)Tt * Bb * Uu]; __device__ bf g_t1l[(size_t)Tt * Bb * Uu];
__device__ bf g_xh[(size_t)Bb * Tt * Ff];  __device__ bf g_xl[(size_t)Bb * Tt * Ff];
// weights transposed to [n][k] and split hi/lo
__device__ bf g_whTh[(size_t)N4 * Uu]; __device__ bf g_whTl[(size_t)N4 * Uu];
__device__ bf g_wdTh[(size_t)N4 * Uu]; __device__ bf g_wdTl[(size_t)N4 * Uu];
__device__ bf g_wxTh[(size_t)N4 * Ff]; __device__ bf g_wxTl[(size_t)N4 * Ff];
__device__ bf g_d1Th[(size_t)Uu * Uu]; __device__ bf g_d1Tl[(size_t)Uu * Uu];
__device__ bf g_d2Th[(size_t)Ff * Uu]; __device__ bf g_d2Tl[(size_t)Ff * Uu];
__device__ unsigned int g_bar;

// ---------------- helpers ----------------------------------------------------
__device__ __forceinline__ void split_bf(float v, bf& hi, bf& lo) {
    hi = __float2bfloat16_rn(v);
    lo = __float2bfloat16_rn(v - __bfloat162float(hi));
}

__device__ __forceinline__ void mma16(float c[4], const unsigned int a[4],
                                      const unsigned int b[2]) {
    asm volatile(
        "mma.sync.aligned.m16n8k16.row.col.f32.bf16.bf16.f32 "
        "{%0,%1,%2,%3}, {%4,%5,%6,%7}, {%8,%9}, {%0,%1,%2,%3};"
        : "+f"(c[0]), "+f"(c[1]), "+f"(c[2]), "+f"(c[3])
        : "r"(a[0]), "r"(a[1]), "r"(a[2]), "r"(a[3]), "r"(b[0]), "r"(b[1]));
}

__device__ __forceinline__ float sigmoidf_(float x) {
    return 1.f / (1.f + __expf(-x));
}

__device__ __forceinline__ void cpa16(void* s, const void* g) {
    // cg: bypass L1 — required: persistent kernel, h re-read across steps.
    unsigned int sa = (unsigned int)__cvta_generic_to_shared(s);
    asm volatile("cp.async.cg.shared.global [%0], [%1], 16;" :: "r"(sa), "l"(g));
}

// ---------------- prep: split to bf16 hi/lo, transpose weights ---------------
__global__ void __launch_bounds__(256) prep_kernel(
        const float* __restrict__ x,
        const float* __restrict__ ewx, const float* __restrict__ ewh,
        const float* __restrict__ dwx, const float* __restrict__ dwh,
        const float* __restrict__ d1w, const float* __restrict__ d2w) {
    int i = blockIdx.x * blockDim.x + threadIdx.x;
    if (i == 0) g_bar = 0u;
    if (i < Bb * Tt * Ff) split_bf(x[i], g_xh[i], g_xl[i]);
    if (i < N4 * Uu) {                     // i = k*4096 + n  (coalesced reads)
        int k = i >> 12, n = i & 4095;
        size_t o = (size_t)n * Uu + k;
        split_bf(ewh[i],          g_whTh[o], g_whTl[o]);
        split_bf(dwx[i] + dwh[i], g_wdTh[o], g_wdTl[o]);
    }
    if (i < N4 * Ff) {                     // i = k*4096 + n, k < 128
        int k = i >> 12, n = i & 4095;
        size_t o = (size_t)n * Ff + k;
        split_bf(ewx[i], g_wxTh[o], g_wxTl[o]);
    }
    if (i < Uu * Uu) {                     // i = k*1024 + n
        int k = i >> 10, n = i & 1023;
        size_t o = (size_t)n * Uu + k;
        split_bf(d1w[i], g_d1Th[o], g_d1Tl[o]);
    }
    if (i < Uu * Ff) {                     // i = k*128 + n
        int k = i >> 7, n = i & 127;
        size_t o = (size_t)n * Uu + k;
        split_bf(d2w[i], g_d2Th[o], g_d2Tl[o]);
    }
    if (i < Bb * Uu) {
        g_h0h[i] = __float2bfloat16(0.f); g_h0l[i] = __float2bfloat16(0.f);
    }
}

// ---------------- persistent recurrence kernel --------------------------------
// 128 CTAs (32 u-tiles x 4 m-tiles), 256 threads, grid barrier between steps.
// bf16x3: z = Ah@Bh + Al@Bh + Ah@Bl, fp32 accum. 4-stage cp.async ring.
struct SmP {
    bf Ah[4][64][40];                      // 20480 B (80B rows: bank-conflict-free)
    bf Al[4][64][40];                      // 20480 B
    union {
        struct { bf Bh[4][128][40]; bf Bl[4][128][40]; } b;   // 81920 B
        float Z[64][132];                  // 33792 B (aliases B; used post-GEMM)
    } u;
};
#define SMEMP_BYTES (sizeof(SmP))

__device__ __forceinline__ void prefetch_tiles(SmP* sm, int st,
        const bf* Ah, const bf* Al, int lda,
        const bf* Bh, const bf* Bl, int ldb, int u0, int tid) {
    {   // A: 64 rows x 32 halves = 64B/row = 4 x 16B
        int row = tid >> 2, seg = (tid & 3) * 8;
        cpa16(&sm->Ah[st][row][seg], Ah + (size_t)row * lda + seg);
        cpa16(&sm->Al[st][row][seg], Al + (size_t)row * lda + seg);
    }
#pragma unroll
    for (int s = 0; s < 2; s++) {          // B: 128 n-rows x 32 halves
        int idx = tid + s * 256;
        int nn = idx >> 2, seg = (idx & 3) * 8;
        int g = ((nn >> 5) << 10) + u0 + (nn & 31);   // gate*1024 + u
        cpa16(&sm->u.b.Bh[st][nn][seg], Bh + (size_t)g * ldb + seg);
        cpa16(&sm->u.b.Bl[st][nn][seg], Bl + (size_t)g * ldb + seg);
    }
    asm volatile("cp.async.commit_group;");
}

__global__ void __launch_bounds__(256) lstm_persist(const float* __restrict__ eb,
                                                    const float* __restrict__ db) {
    extern __shared__ char smraw[];
    SmP* sm = (SmP*)smraw;
    const int u0 = blockIdx.x * 32;
    const int m0 = blockIdx.y * 64;
    const int tid = threadIdx.x, lane = tid & 31, wid = tid >> 5;
    const int wm = wid >> 2, wn = wid & 3, r = lane >> 2, q = lane & 3;

    float c_reg[8];                        // cell state lives in registers: the
#pragma unroll                             // CTA<->(m,u) tile map is fixed for
    for (int s = 0; s < 8; s++) c_reg[s] = 0.f;   // all 1024 steps.

    for (int t = 0; t < 2 * Tt; t++) {
        const int is_dec = (t >= Tt);
        const bf *hih, *hil;
        bf *hoh, *hol;
        const bf *Wh, *Wl;
        const float* bias;
        int NC, ts;
        if (is_dec) {
            ts = t - Tt;
            Wh = g_wdTh; Wl = g_wdTl; bias = db; NC = 32;
            if (ts == 0) { hih = g_h0h; hil = g_h0l; }
            else { hih = g_hsh + (size_t)(ts - 1) * Bb * Uu;
                   hil = g_hsl + (size_t)(ts - 1) * Bb * Uu; }
            hoh = g_hsh + (size_t)ts * Bb * Uu;
            hol = g_hsl + (size_t)ts * Bb * Uu;
        } else {
            ts = t;
            Wh = g_whTh; Wl = g_whTl; bias = eb; NC = 36;  // 32 h + 4 x chunks
            if (ts & 1) { hih = g_h1h; hil = g_h1l; hoh = g_h0h; hol = g_h0l; }
            else        { hih = g_h0h; hil = g_h0l; hoh = g_h1h; hol = g_h1l; }
        }

        float acc[2][4][4];
#pragma unroll
        for (int a = 0; a < 2; a++)
#pragma unroll
            for (int b = 0; b < 4; b++)
#pragma unroll
                for (int e = 0; e < 4; e++) acc[a][b][e] = 0.f;

        auto getAB = [&](int c, const bf*& Ah_, const bf*& Al_, int& lda,
                         const bf*& Bh_, const bf*& Bl_, int& ldb) {
            if (c < 32) {
                Ah_ = hih + (size_t)m0 * Uu + c * 32;
                Al_ = hil + (size_t)m0 * Uu + c * 32;
                lda = Uu;
                Bh_ = Wh + c * 32; Bl_ = Wl + c * 32; ldb = Uu;
            } else {
                int cc = c - 32;
                size_t off = (size_t)m0 * (Tt * Ff) + (size_t)ts * Ff + cc * 32;
                Ah_ = g_xh + off; Al_ = g_xl + off; lda = Tt * Ff;
                Bh_ = g_wxTh + cc * 32; Bl_ = g_wxTl + cc * 32; ldb = Ff;
            }
        };

        // prologue: fill 3 stages (NC >= 32 > 3 always)
#pragma unroll
        for (int p = 0; p < 3; p++) {
            const bf *Ah_, *Al_, *Bh_, *Bl_; int lda, ldb;
            getAB(p, Ah_, Al_, lda, Bh_, Bl_, ldb);
            prefetch_tiles(sm, p, Ah_, Al_, lda, Bh_, Bl_, ldb, u0, tid);
        }

        for (int c = 0; c < NC; c++) {
            asm volatile("cp.async.wait_group 2;");   // group c done (1 group/chunk)
            __syncthreads();
            if (c + 3 < NC) {
                const bf *Ah_, *Al_, *Bh_, *Bl_; int lda, ldb;
                getAB(c + 3, Ah_, Al_, lda, Bh_, Bl_, ldb);
                prefetch_tiles(sm, (c + 3) & 3, Ah_, Al_, lda, Bh_, Bl_, ldb, u0, tid);
            } else {
                asm volatile("cp.async.commit_group;");   // empty: keep group==chunk
            }
            const int st = c & 3;
#pragma unroll
            for (int kh = 0; kh < 2; kh++) {
                const int kb = kh * 16;
                unsigned int ah[2][4], al[2][4], bh[4][2], bl[4][2];
#pragma unroll
                for (int mb = 0; mb < 2; mb++) {
                    int row = wm * 32 + mb * 16;
                    ah[mb][0] = *(const unsigned int*)&sm->Ah[st][row + r    ][kb + 2 * q];
                    ah[mb][1] = *(const unsigned int*)&sm->Ah[st][row + r + 8][kb + 2 * q];
                    ah[mb][2] = *(const unsigned int*)&sm->Ah[st][row + r    ][kb + 2 * q + 8];
                    ah[mb][3] = *(const unsigned int*)&sm->Ah[st][row + r + 8][kb + 2 * q + 8];
                    al[mb][0] = *(const unsigned int*)&sm->Al[st][row + r    ][kb + 2 * q];
                    al[mb][1] = *(const unsigned int*)&sm->Al[st][row + r + 8][kb + 2 * q];
                    al[mb][2] = *(const unsigned int*)&sm->Al[st][row + r    ][kb + 2 * q + 8];
                    al[mb][3] = *(const unsigned int*)&sm->Al[st][row + r + 8][kb + 2 * q + 8];
                }
#pragma unroll
                for (int nb = 0; nb < 4; nb++) {
                    int col = wn * 32 + nb * 8 + r;
                    bh[nb][0] = *(const unsigned int*)&sm->u.b.Bh[st][col][kb + 2 * q];
                    bh[nb][1] = *(const unsigned int*)&sm->u.b.Bh[st][col][kb + 2 * q + 8];
                    bl[nb][0] = *(const unsigned int*)&sm->u.b.Bl[st][col][kb + 2 * q];
                    bl[nb][1] = *(const unsigned int*)&sm->u.b.Bl[st][col][kb + 2 * q + 8];
                }
                // pass-outer ordering: same per-accumulator sequence (hh,lh,hl)
                // as before => numerics identical; reuse distance 2 -> 8 mma.
#pragma unroll
                for (int nb = 0; nb < 4; nb++) {
                    mma16(acc[0][nb], ah[0], bh[nb]);
                    mma16(acc[1][nb], ah[1], bh[nb]);
                }
#pragma unroll
                for (int nb = 0; nb < 4; nb++) {
                    mma16(acc[0][nb], al[0], bh[nb]);
                    mma16(acc[1][nb], al[1], bh[nb]);
                }
#pragma unroll
                for (int nb = 0; nb < 4; nb++) {
                    mma16(acc[0][nb], ah[0], bl[nb]);
                    mma16(acc[1][nb], ah[1], bl[nb]);
                }
            }
        }
        asm volatile("cp.async.wait_group 0;");
        __syncthreads();                   // all compute done before Z aliases B

        // stage z through smem so each thread gathers all 4 gates of one (b,u)
#pragma unroll
        for (int mb = 0; mb < 2; mb++)
#pragma unroll
            for (int nb = 0; nb < 4; nb++) {
                int row = wm * 32 + mb * 16 + r;
                int col = wn * 32 + nb * 8 + 2 * q;
                sm->u.Z[row    ][col    ] = acc[mb][nb][0];
                sm->u.Z[row    ][col + 1] = acc[mb][nb][1];
                sm->u.Z[row + 8][col    ] = acc[mb][nb][2];
                sm->u.Z[row + 8][col + 1] = acc[mb][nb][3];
            }
        __syncthreads();

#pragma unroll
        for (int s = 0; s < 8; s++) {
            int idx = tid + s * 256;
            int i = idx >> 5, j = idx & 31;
            int u = u0 + j;
            float zi = sm->u.Z[i][j     ] + bias[u];
            float zf = sm->u.Z[i][j + 32] + bias[u + 1024];
            float zg = sm->u.Z[i][j + 64] + bias[u + 2048];
            float zo = sm->u.Z[i][j + 96] + bias[u + 3072];
            float ig = sigmoidf_(zi);
            float fg = sigmoidf_(zf);
            float gg = tanhf(zg);
            float og = sigmoidf_(zo);
            float cn = fg * c_reg[s] + ig * gg;
            c_reg[s] = cn;
            float h = og * tanhf(cn);
            size_t gi = (size_t)(m0 + i) * Uu + u;
            split_bf(h, hoh[gi], hol[gi]);
        }

        // -------- grid barrier: 128 CTAs all co-resident (1 wave on 148 SMs) --
        __syncthreads();
        if (tid == 0) {
            __threadfence();
            atomicAdd(&g_bar, 1u);
            unsigned int target = 128u * (unsigned int)(t + 1);
            while (*((volatile unsigned int*)&g_bar) < target) __nanosleep(64);
            __threadfence();
        }
        __syncthreads();
    }
}

// ---------------- dense epilogue GEMMs (bf16x3) -------------------------------
// SRC==0: t1 = split(relu(hs @ d1W + d1b)), N=1024
// SRC==1: out =          t1 @ d2W + d2b   , N=128, store permuted [T,B]->[B,T]
template <int SRC>
__global__ void __launch_bounds__(256) dense_kernel(const float* __restrict__ bias,
                                                    float* __restrict__ outp) {
    const bf* Agh = (SRC == 0) ? g_hsh : g_t1h;
    const bf* Agl = (SRC == 0) ? g_hsl : g_t1l;
    const bf* Bgh = (SRC == 0) ? g_d1Th : g_d2Th;
    const bf* Bgl = (SRC == 0) ? g_d1Tl : g_d2Tl;
    __shared__ bf Ash[64][40], Asl[64][40], Bsh[64][40], Bsl[64][40];
    const int n0 = blockIdx.x * 64;
    const int m0 = blockIdx.y * 64;
    const int tid = threadIdx.x, lane = tid & 31, wid = tid >> 5;
    const int wm = wid >> 2, wn = wid & 3, r = lane >> 2, q = lane & 3;

    float acc[2][2][4];
#pragma unroll
    for (int a = 0; a < 2; a++)
#pragma unroll
        for (int b = 0; b < 2; b++)
#pragma unroll
            for (int e = 0; e < 4; e++) acc[a][b][e] = 0.f;

    const int row = tid >> 2, seg = (tid & 3) * 8;
    for (int k0 = 0; k0 < 1024; k0 += 32) {
        __syncthreads();
        *(uint4*)&Ash[row][seg] = *(const uint4*)(Agh + (size_t)(m0 + row) * 1024 + k0 + seg);
        *(uint4*)&Asl[row][seg] = *(const uint4*)(Agl + (size_t)(m0 + row) * 1024 + k0 + seg);
        *(uint4*)&Bsh[row][seg] = *(const uint4*)(Bgh + (size_t)(n0 + row) * 1024 + k0 + seg);
        *(uint4*)&Bsl[row][seg] = *(const uint4*)(Bgl + (size_t)(n0 + row) * 1024 + k0 + seg);
        __syncthreads();
#pragma unroll
        for (int kh = 0; kh < 2; kh++) {
            const int kb = kh * 16;
            unsigned int ah[2][4], al[2][4], bh[2][2], bl[2][2];
#pragma unroll
            for (int mb = 0; mb < 2; mb++) {
                int rw = wm * 32 + mb * 16;
                ah[mb][0] = *(const unsigned int*)&Ash[rw + r    ][kb + 2 * q];
                ah[mb][1] = *(const unsigned int*)&Ash[rw + r + 8][kb + 2 * q];
                ah[mb][2] = *(const unsigned int*)&Ash[rw + r    ][kb + 2 * q + 8];
                ah[mb][3] = *(const unsigned int*)&Ash[rw + r + 8][kb + 2 * q + 8];
                al[mb][0] = *(const unsigned int*)&Asl[rw + r    ][kb + 2 * q];
                al[mb][1] = *(const unsigned int*)&Asl[rw + r + 8][kb + 2 * q];
                al[mb][2] = *(const unsigned int*)&Asl[rw + r    ][kb + 2 * q + 8];
                al[mb][3] = *(const unsigned int*)&Asl[rw + r + 8][kb + 2 * q + 8];
            }
#pragma unroll
            for (int nb = 0; nb < 2; nb++) {
                int col = wn * 16 + nb * 8 + r;
                bh[nb][0] = *(const unsigned int*)&Bsh[col][kb + 2 * q];
                bh[nb][1] = *(const unsigned int*)&Bsh[col][kb + 2 * q + 8];
                bl[nb][0] = *(const unsigned int*)&Bsl[col][kb + 2 * q];
                bl[nb][1] = *(const unsigned int*)&Bsl[col][kb + 2 * q + 8];
            }
#pragma unroll
            for (int nb = 0; nb < 2; nb++) {
                mma16(acc[0][nb], ah[0], bh[nb]);
                mma16(acc[1][nb], ah[1], bh[nb]);
            }
#pragma unroll
            for (int nb = 0; nb < 2; nb++) {
                mma16(acc[0][nb], al[0], bh[nb]);
                mma16(acc[1][nb], al[1], bh[nb]);
            }
#pragma unroll
            for (int nb = 0; nb < 2; nb++) {
                mma16(acc[0][nb], ah[0], bl[nb]);
                mma16(acc[1][nb], ah[1], bl[nb]);
            }
        }
    }

#pragma unroll
    for (int mb = 0; mb < 2; mb++)
#pragma unroll
        for (int nb = 0; nb < 2; nb++) {
            int rwb = m0 + wm * 32 + mb * 16 + r;
            int cwb = n0 + wn * 16 + nb * 8 + 2 * q;
#pragma unroll
            for (int e = 0; e < 4; e++) {
                int rr = rwb + (e >> 1) * 8;
                int cc = cwb + (e & 1);
                float v = acc[mb][nb][e] + bias[cc];
                if (SRC == 0) {
                    v = fmaxf(v, 0.f);
                    size_t o = (size_t)rr * 1024 + cc;
                    split_bf(v, g_t1h[o], g_t1l[o]);
                } else {
                    int tt = rr >> 8, bb = rr & 255;   // row = t*256 + b
                    outp[((size_t)bb * Tt + tt) * Ff + cc] = v;
                }
            }
        }
}

// ---------------- launch ------------------------------------------------------
extern "C" void kernel_launch(void* const* d_in, const int* in_sizes, int n_in,
                              void* d_out, int out_size) {
    const float* x   = (const float*)d_in[0];
    const float* ewx = (const float*)d_in[1];
    const float* ewh = (const float*)d_in[2];
    const float* eb  = (const float*)d_in[3];
    const float* dwx = (const float*)d_in[4];
    const float* dwh = (const float*)d_in[5];
    const float* db  = (const float*)d_in[6];
    const float* d1w = (const float*)d_in[7];
    const float* d1b = (const float*)d_in[8];
    const float* d2w = (const float*)d_in[9];
    const float* d2b = (const float*)d_in[10];
    float* out = (float*)d_out;

    cudaFuncSetAttribute(lstm_persist, cudaFuncAttributeMaxDynamicSharedMemorySize,
                         (int)SMEMP_BYTES);

    prep_kernel<<<(Bb * Tt * Ff + 255) / 256, 256>>>(x, ewx, ewh, dwx, dwh, d1w, d2w);

    dim3 sgrid(Uu / 32, Bb / 64);   // 128 CTAs: single wave on 148 SMs
    lstm_persist<<<sgrid, 256, SMEMP_BYTES>>>(eb, db);

    dense_kernel<0><<<dim3(1024 / 64, (Tt * Bb) / 64), 256>>>(d1b, nullptr);
    dense_kernel<1><<<dim3(128 / 64, (Tt * Bb) / 64), 256>>>(d2b, out);
}

// round 8
// speedup vs baseline: 1.3556x; 1.0002x over previous
#include <cuda_runtime.h>
#include <cuda_bf16.h>

#define Bb 256
#define Tt 512
#define Ff 128
#define Uu 1024
#define N4 4096

typedef __nv_bfloat16 bf;

// ---------------- scratch (static device globals; no allocation) -------------
__device__ bf g_h0h[Bb * Uu]; __device__ bf g_h0l[Bb * Uu];
__device__ bf g_h1h[Bb * Uu]; __device__ bf g_h1l[Bb * Uu];
__device__ bf g_hsh[(size_t)Tt * Bb * Uu]; __device__ bf g_hsl[(size_t)Tt * Bb * Uu];
__device__ bf g_t1h[(size_t)Tt * Bb * Uu]; __device__ bf g_t1l[(size_t)Tt * Bb * Uu];
__device__ bf g_xh[(size_t)Bb * Tt * Ff];  __device__ bf g_xl[(size_t)Bb * Tt * Ff];
// weights transposed to [n][k] and split hi/lo
__device__ bf g_whTh[(size_t)N4 * Uu]; __device__ bf g_whTl[(size_t)N4 * Uu];
__device__ bf g_wdTh[(size_t)N4 * Uu]; __device__ bf g_wdTl[(size_t)N4 * Uu];
__device__ bf g_wxTh[(size_t)N4 * Ff]; __device__ bf g_wxTl[(size_t)N4 * Ff];
__device__ bf g_d1Th[(size_t)Uu * Uu]; __device__ bf g_d1Tl[(size_t)Uu * Uu];
__device__ bf g_d2Th[(size_t)Ff * Uu]; __device__ bf g_d2Tl[(size_t)Ff * Uu];
__device__ unsigned int g_bar;

// ---------------- helpers ----------------------------------------------------
__device__ __forceinline__ void split_bf(float v, bf& hi, bf& lo) {
    hi = __float2bfloat16_rn(v);
    lo = __float2bfloat16_rn(v - __bfloat162float(hi));
}

__device__ __forceinline__ void mma16(float c[4], const unsigned int a[4],
                                      const unsigned int b[2]) {
    asm volatile(
        "mma.sync.aligned.m16n8k16.row.col.f32.bf16.bf16.f32 "
        "{%0,%1,%2,%3}, {%4,%5,%6,%7}, {%8,%9}, {%0,%1,%2,%3};"
        : "+f"(c[0]), "+f"(c[1]), "+f"(c[2]), "+f"(c[3])
        : "r"(a[0]), "r"(a[1]), "r"(a[2]), "r"(a[3]), "r"(b[0]), "r"(b[1]));
}

__device__ __forceinline__ float sigmoidf_(float x) {
    return 1.f / (1.f + __expf(-x));
}

__device__ __forceinline__ void cpa16(void* s, const void* g) {
    // cg: bypass L1 — required: persistent kernel, h re-read across steps.
    unsigned int sa = (unsigned int)__cvta_generic_to_shared(s);
    asm volatile("cp.async.cg.shared.global [%0], [%1], 16;" :: "r"(sa), "l"(g));
}

// ---------------- prep: split to bf16 hi/lo, transpose weights ---------------
__global__ void __launch_bounds__(256) prep_kernel(
        const float* __restrict__ x,
        const float* __restrict__ ewx, const float* __restrict__ ewh,
        const float* __restrict__ dwx, const float* __restrict__ dwh,
        const float* __restrict__ d1w, const float* __restrict__ d2w) {
    int i = blockIdx.x * blockDim.x + threadIdx.x;
    if (i == 0) g_bar = 0u;
    if (i < Bb * Tt * Ff) split_bf(x[i], g_xh[i], g_xl[i]);
    if (i < N4 * Uu) {                     // i = k*4096 + n  (coalesced reads)
        int k = i >> 12, n = i & 4095;
        size_t o = (size_t)n * Uu + k;
        split_bf(ewh[i],          g_whTh[o], g_whTl[o]);
        split_bf(dwx[i] + dwh[i], g_wdTh[o], g_wdTl[o]);
    }
    if (i < N4 * Ff) {                     // i = k*4096 + n, k < 128
        int k = i >> 12, n = i & 4095;
        size_t o = (size_t)n * Ff + k;
        split_bf(ewx[i], g_wxTh[o], g_wxTl[o]);
    }
    if (i < Uu * Uu) {                     // i = k*1024 + n
        int k = i >> 10, n = i & 1023;
        size_t o = (size_t)n * Uu + k;
        split_bf(d1w[i], g_d1Th[o], g_d1Tl[o]);
    }
    if (i < Uu * Ff) {                     // i = k*128 + n
        int k = i >> 7, n = i & 127;
        size_t o = (size_t)n * Uu + k;
        split_bf(d2w[i], g_d2Th[o], g_d2Tl[o]);
    }
    if (i < Bb * Uu) {
        g_h0h[i] = __float2bfloat16(0.f); g_h0l[i] = __float2bfloat16(0.f);
    }
}

// ---------------- persistent recurrence kernel --------------------------------
// 128 CTAs (32 u-tiles x 4 m-tiles), 256 threads, grid barrier between steps.
// bf16x3: z = Ah@Bh + Al@Bh + Ah@Bl, fp32 accum. 4-stage cp.async ring.
struct SmP {
    bf Ah[4][64][40];                      // 20480 B (80B rows: bank-conflict-free)
    bf Al[4][64][40];                      // 20480 B
    union {
        struct { bf Bh[4][128][40]; bf Bl[4][128][40]; } b;   // 81920 B
        float Z[64][132];                  // 33792 B (aliases B; used post-GEMM)
    } u;
};
#define SMEMP_BYTES (sizeof(SmP))

__device__ __forceinline__ void prefetch_tiles(SmP* sm, int st,
        const bf* Ah, const bf* Al, int lda,
        const bf* Bh, const bf* Bl, int ldb, int u0, int tid) {
    {   // A: 64 rows x 32 halves = 64B/row = 4 x 16B
        int row = tid >> 2, seg = (tid & 3) * 8;
        cpa16(&sm->Ah[st][row][seg], Ah + (size_t)row * lda + seg);
        cpa16(&sm->Al[st][row][seg], Al + (size_t)row * lda + seg);
    }
#pragma unroll
    for (int s = 0; s < 2; s++) {          // B: 128 n-rows x 32 halves
        int idx = tid + s * 256;
        int nn = idx >> 2, seg = (idx & 3) * 8;
        int g = ((nn >> 5) << 10) + u0 + (nn & 31);   // gate*1024 + u
        cpa16(&sm->u.b.Bh[st][nn][seg], Bh + (size_t)g * ldb + seg);
        cpa16(&sm->u.b.Bl[st][nn][seg], Bl + (size_t)g * ldb + seg);
    }
    asm volatile("cp.async.commit_group;");
}

__global__ void __launch_bounds__(256) lstm_persist(const float* __restrict__ eb,
                                                    const float* __restrict__ db) {
    extern __shared__ char smraw[];
    SmP* sm = (SmP*)smraw;
    const int u0 = blockIdx.x * 32;
    const int m0 = blockIdx.y * 64;
    const int tid = threadIdx.x, lane = tid & 31, wid = tid >> 5;
    const int wm = wid >> 2, wn = wid & 3, r = lane >> 2, q = lane & 3;

    float c_reg[8];                        // cell state lives in registers: the
#pragma unroll                             // CTA<->(m,u) tile map is fixed for
    for (int s = 0; s < 8; s++) c_reg[s] = 0.f;   // all 1024 steps.

    for (int t = 0; t < 2 * Tt; t++) {
        const int is_dec = (t >= Tt);
        const bf *hih, *hil;
        bf *hoh, *hol;
        const bf *Wh, *Wl;
        const float* bias;
        int NC, ts;
        if (is_dec) {
            ts = t - Tt;
            Wh = g_wdTh; Wl = g_wdTl; bias = db; NC = 32;
            if (ts == 0) { hih = g_h0h; hil = g_h0l; }
            else { hih = g_hsh + (size_t)(ts - 1) * Bb * Uu;
                   hil = g_hsl + (size_t)(ts - 1) * Bb * Uu; }
            hoh = g_hsh + (size_t)ts * Bb * Uu;
            hol = g_hsl + (size_t)ts * Bb * Uu;
        } else {
            ts = t;
            Wh = g_whTh; Wl = g_whTl; bias = eb; NC = 36;  // 32 h + 4 x chunks
            if (ts & 1) { hih = g_h1h; hil = g_h1l; hoh = g_h0h; hol = g_h0l; }
            else        { hih = g_h0h; hil = g_h0l; hoh = g_h1h; hol = g_h1l; }
        }

        float acc[2][4][4];
#pragma unroll
        for (int a = 0; a < 2; a++)
#pragma unroll
            for (int b = 0; b < 4; b++)
#pragma unroll
                for (int e = 0; e < 4; e++) acc[a][b][e] = 0.f;

        auto getAB = [&](int c, const bf*& Ah_, const bf*& Al_, int& lda,
                         const bf*& Bh_, const bf*& Bl_, int& ldb) {
            if (c < 32) {
                Ah_ = hih + (size_t)m0 * Uu + c * 32;
                Al_ = hil + (size_t)m0 * Uu + c * 32;
                lda = Uu;
                Bh_ = Wh + c * 32; Bl_ = Wl + c * 32; ldb = Uu;
            } else {
                int cc = c - 32;
                size_t off = (size_t)m0 * (Tt * Ff) + (size_t)ts * Ff + cc * 32;
                Ah_ = g_xh + off; Al_ = g_xl + off; lda = Tt * Ff;
                Bh_ = g_wxTh + cc * 32; Bl_ = g_wxTl + cc * 32; ldb = Ff;
            }
        };

        // prologue: fill 3 stages (NC >= 32 > 3 always)
#pragma unroll
        for (int p = 0; p < 3; p++) {
            const bf *Ah_, *Al_, *Bh_, *Bl_; int lda, ldb;
            getAB(p, Ah_, Al_, lda, Bh_, Bl_, ldb);
            prefetch_tiles(sm, p, Ah_, Al_, lda, Bh_, Bl_, ldb, u0, tid);
        }

        for (int c = 0; c < NC; c++) {
            asm volatile("cp.async.wait_group 2;");   // group c done (1 group/chunk)
            __syncthreads();
            if (c + 3 < NC) {
                const bf *Ah_, *Al_, *Bh_, *Bl_; int lda, ldb;
                getAB(c + 3, Ah_, Al_, lda, Bh_, Bl_, ldb);
                prefetch_tiles(sm, (c + 3) & 3, Ah_, Al_, lda, Bh_, Bl_, ldb, u0, tid);
            } else {
                asm volatile("cp.async.commit_group;");   // empty: keep group==chunk
            }
            const int st = c & 3;
#pragma unroll
            for (int kh = 0; kh < 2; kh++) {
                const int kb = kh * 16;
                unsigned int ah[2][4], al[2][4], bh[4][2], bl[4][2];
#pragma unroll
                for (int mb = 0; mb < 2; mb++) {
                    int row = wm * 32 + mb * 16;
                    ah[mb][0] = *(const unsigned int*)&sm->Ah[st][row + r    ][kb + 2 * q];
                    ah[mb][1] = *(const unsigned int*)&sm->Ah[st][row + r + 8][kb + 2 * q];
                    ah[mb][2] = *(const unsigned int*)&sm->Ah[st][row + r    ][kb + 2 * q + 8];
                    ah[mb][3] = *(const unsigned int*)&sm->Ah[st][row + r + 8][kb + 2 * q + 8];
                    al[mb][0] = *(const unsigned int*)&sm->Al[st][row + r    ][kb + 2 * q];
                    al[mb][1] = *(const unsigned int*)&sm->Al[st][row + r + 8][kb + 2 * q];
                    al[mb][2] = *(const unsigned int*)&sm->Al[st][row + r    ][kb + 2 * q + 8];
                    al[mb][3] = *(const unsigned int*)&sm->Al[st][row + r + 8][kb + 2 * q + 8];
                }
#pragma unroll
                for (int nb = 0; nb < 4; nb++) {
                    int col = wn * 32 + nb * 8 + r;
                    bh[nb][0] = *(const unsigned int*)&sm->u.b.Bh[st][col][kb + 2 * q];
                    bh[nb][1] = *(const unsigned int*)&sm->u.b.Bh[st][col][kb + 2 * q + 8];
                    bl[nb][0] = *(const unsigned int*)&sm->u.b.Bl[st][col][kb + 2 * q];
                    bl[nb][1] = *(const unsigned int*)&sm->u.b.Bl[st][col][kb + 2 * q + 8];
                }
                // pass-outer ordering: same per-accumulator sequence (hh,lh,hl)
                // as before => numerics identical; reuse distance 2 -> 8 mma.
#pragma unroll
                for (int nb = 0; nb < 4; nb++) {
                    mma16(acc[0][nb], ah[0], bh[nb]);
                    mma16(acc[1][nb], ah[1], bh[nb]);
                }
#pragma unroll
                for (int nb = 0; nb < 4; nb++) {
                    mma16(acc[0][nb], al[0], bh[nb]);
                    mma16(acc[1][nb], al[1], bh[nb]);
                }
#pragma unroll
                for (int nb = 0; nb < 4; nb++) {
                    mma16(acc[0][nb], ah[0], bl[nb]);
                    mma16(acc[1][nb], ah[1], bl[nb]);
                }
            }
        }
        asm volatile("cp.async.wait_group 0;");
        __syncthreads();                   // all compute done before Z aliases B

        // stage z through smem so each thread gathers all 4 gates of one (b,u)
#pragma unroll
        for (int mb = 0; mb < 2; mb++)
#pragma unroll
            for (int nb = 0; nb < 4; nb++) {
                int row = wm * 32 + mb * 16 + r;
                int col = wn * 32 + nb * 8 + 2 * q;
                sm->u.Z[row    ][col    ] = acc[mb][nb][0];
                sm->u.Z[row    ][col + 1] = acc[mb][nb][1];
                sm->u.Z[row + 8][col    ] = acc[mb][nb][2];
                sm->u.Z[row + 8][col + 1] = acc[mb][nb][3];
            }
        __syncthreads();

#pragma unroll
        for (int s = 0; s < 8; s++) {
            int idx = tid + s * 256;
            int i = idx >> 5, j = idx & 31;
            int u = u0 + j;
            float zi = sm->u.Z[i][j     ] + bias[u];
            float zf = sm->u.Z[i][j + 32] + bias[u + 1024];
            float zg = sm->u.Z[i][j + 64] + bias[u + 2048];
            float zo = sm->u.Z[i][j + 96] + bias[u + 3072];
            float ig = sigmoidf_(zi);
            float fg = sigmoidf_(zf);
            float gg = tanhf(zg);
            float og = sigmoidf_(zo);
            float cn = fg * c_reg[s] + ig * gg;
            c_reg[s] = cn;
            float h = og * tanhf(cn);
            size_t gi = (size_t)(m0 + i) * Uu + u;
            split_bf(h, hoh[gi], hol[gi]);
        }

        // -------- grid barrier: 128 CTAs all co-resident (1 wave on 148 SMs) --
        __syncthreads();
        if (tid == 0) {
            __threadfence();
            atomicAdd(&g_bar, 1u);
            unsigned int target = 128u * (unsigned int)(t + 1);
            while (*((volatile unsigned int*)&g_bar) < target) __nanosleep(64);
            __threadfence();
        }
        __syncthreads();
    }
}

// ---------------- dense epilogue GEMMs (bf16x3) -------------------------------
// SRC==0: t1 = split(relu(hs @ d1W + d1b)), N=1024
// SRC==1: out =          t1 @ d2W + d2b   , N=128, store permuted [T,B]->[B,T]
template <int SRC>
__global__ void __launch_bounds__(256) dense_kernel(const float* __restrict__ bias,
                                                    float* __restrict__ outp) {
    const bf* Agh = (SRC == 0) ? g_hsh : g_t1h;
    const bf* Agl = (SRC == 0) ? g_hsl : g_t1l;
    const bf* Bgh = (SRC == 0) ? g_d1Th : g_d2Th;
    const bf* Bgl = (SRC == 0) ? g_d1Tl : g_d2Tl;
    __shared__ bf Ash[64][40], Asl[64][40], Bsh[64][40], Bsl[64][40];
    const int n0 = blockIdx.x * 64;
    const int m0 = blockIdx.y * 64;
    const int tid = threadIdx.x, lane = tid & 31, wid = tid >> 5;
    const int wm = wid >> 2, wn = wid & 3, r = lane >> 2, q = lane & 3;

    float acc[2][2][4];
#pragma unroll
    for (int a = 0; a < 2; a++)
#pragma unroll
        for (int b = 0; b < 2; b++)
#pragma unroll
            for (int e = 0; e < 4; e++) acc[a][b][e] = 0.f;

    const int row = tid >> 2, seg = (tid & 3) * 8;
    for (int k0 = 0; k0 < 1024; k0 += 32) {
        __syncthreads();
        *(uint4*)&Ash[row][seg] = *(const uint4*)(Agh + (size_t)(m0 + row) * 1024 + k0 + seg);
        *(uint4*)&Asl[row][seg] = *(const uint4*)(Agl + (size_t)(m0 + row) * 1024 + k0 + seg);
        *(uint4*)&Bsh[row][seg] = *(const uint4*)(Bgh + (size_t)(n0 + row) * 1024 + k0 + seg);
        *(uint4*)&Bsl[row][seg] = *(const uint4*)(Bgl + (size_t)(n0 + row) * 1024 + k0 + seg);
        __syncthreads();
#pragma unroll
        for (int kh = 0; kh < 2; kh++) {
            const int kb = kh * 16;
            unsigned int ah[2][4], al[2][4], bh[2][2], bl[2][2];
#pragma unroll
            for (int mb = 0; mb < 2; mb++) {
                int rw = wm * 32 + mb * 16;
                ah[mb][0] = *(const unsigned int*)&Ash[rw + r    ][kb + 2 * q];
                ah[mb][1] = *(const unsigned int*)&Ash[rw + r + 8][kb + 2 * q];
                ah[mb][2] = *(const unsigned int*)&Ash[rw + r    ][kb + 2 * q + 8];
                ah[mb][3] = *(const unsigned int*)&Ash[rw + r + 8][kb + 2 * q + 8];
                al[mb][0] = *(const unsigned int*)&Asl[rw + r    ][kb + 2 * q];
                al[mb][1] = *(const unsigned int*)&Asl[rw + r + 8][kb + 2 * q];
                al[mb][2] = *(const unsigned int*)&Asl[rw + r    ][kb + 2 * q + 8];
                al[mb][3] = *(const unsigned int*)&Asl[rw + r + 8][kb + 2 * q + 8];
            }
#pragma unroll
            for (int nb = 0; nb < 2; nb++) {
                int col = wn * 16 + nb * 8 + r;
                bh[nb][0] = *(const unsigned int*)&Bsh[col][kb + 2 * q];
                bh[nb][1] = *(const unsigned int*)&Bsh[col][kb + 2 * q + 8];
                bl[nb][0] = *(const unsigned int*)&Bsl[col][kb + 2 * q];
                bl[nb][1] = *(const unsigned int*)&Bsl[col][kb + 2 * q + 8];
            }
#pragma unroll
            for (int nb = 0; nb < 2; nb++) {
                mma16(acc[0][nb], ah[0], bh[nb]);
                mma16(acc[1][nb], ah[1], bh[nb]);
            }
#pragma unroll
            for (int nb = 0; nb < 2; nb++) {
                mma16(acc[0][nb], al[0], bh[nb]);
                mma16(acc[1][nb], al[1], bh[nb]);
            }
#pragma unroll
            for (int nb = 0; nb < 2; nb++) {
                mma16(acc[0][nb], ah[0], bl[nb]);
                mma16(acc[1][nb], ah[1], bl[nb]);
            }
        }
    }

#pragma unroll
    for (int mb = 0; mb < 2; mb++)
#pragma unroll
        for (int nb = 0; nb < 2; nb++) {
            int rwb = m0 + wm * 32 + mb * 16 + r;
            int cwb = n0 + wn * 16 + nb * 8 + 2 * q;
#pragma unroll
            for (int e = 0; e < 4; e++) {
                int rr = rwb + (e >> 1) * 8;
                int cc = cwb + (e & 1);
                float v = acc[mb][nb][e] + bias[cc];
                if (SRC == 0) {
                    v = fmaxf(v, 0.f);
                    size_t o = (size_t)rr * 1024 + cc;
                    split_bf(v, g_t1h[o], g_t1l[o]);
                } else {
                    int tt = rr >> 8, bb = rr & 255;   // row = t*256 + b
                    outp[((size_t)bb * Tt + tt) * Ff + cc] = v;
                }
            }
        }
}

// ---------------- launch ------------------------------------------------------
extern "C" void kernel_launch(void* const* d_in, const int* in_sizes, int n_in,
                              void* d_out, int out_size) {
    const float* x   = (const float*)d_in[0];
    const float* ewx = (const float*)d_in[1];
    const float* ewh = (const float*)d_in[2];
    const float* eb  = (const float*)d_in[3];
    const float* dwx = (const float*)d_in[4];
    const float* dwh = (const float*)d_in[5];
    const float* db  = (const float*)d_in[6];
    const float* d1w = (const float*)d_in[7];
    const float* d1b = (const float*)d_in[8];
    const float* d2w = (const float*)d_in[9];
    const float* d2b = (const float*)d_in[10];
    float* out = (float*)d_out;

    cudaFuncSetAttribute(lstm_persist, cudaFuncAttributeMaxDynamicSharedMemorySize,
                         (int)SMEMP_BYTES);

    prep_kernel<<<(Bb * Tt * Ff + 255) / 256, 256>>>(x, ewx, ewh, dwx, dwh, d1w, d2w);

    dim3 sgrid(Uu / 32, Bb / 64);   // 128 CTAs: single wave on 148 SMs
    lstm_persist<<<sgrid, 256, SMEMP_BYTES>>>(eb, db);

    dense_kernel<0><<<dim3(1024 / 64, (Tt * Bb) / 64), 256>>>(d1b, nullptr);
    dense_kernel<1><<<dim3(128 / 64, (Tt * Bb) / 64), 256>>>(d2b, out);
}